// round 1
// baseline (speedup 1.0000x reference)
#include <cuda_runtime.h>

#define DHEAD 64
#define SEQ   2048
#define EMB   1024
#define NHEAD 16
#define NB    2
#define SCALE 0.03125f        // 1/sqrt(1024)
#define MASKED -3.0e18f       // ~ -1e20/32; identical constant everywhere so an
                              // all-masked row degenerates to uniform softmax (matches ref)

// -------- static device scratch (no allocations allowed) --------
__device__ float g_Qt[(size_t)NB * NHEAD * DHEAD * SEQ]; // [n,h,d,s]
__device__ float g_Kt[(size_t)NB * NHEAD * DHEAD * SEQ]; // [n,h,d,s]
__device__ float g_X [(size_t)NB * SEQ * EMB];           // attention out [m][e]
__device__ float g_Xt[(size_t)EMB * NB * SEQ];           // [e][m]
__device__ float g_Wt[(size_t)EMB * EMB];                // [e][o]

// -------- f32x2 helpers (SASS FFMA2 path — ptxas won't auto-fuse) --------
__device__ __forceinline__ unsigned long long pk2(float x) {
    unsigned long long r;
    asm("mov.b64 %0, {%1, %1};" : "=l"(r) : "f"(x));
    return r;
}
__device__ __forceinline__ void fma2(unsigned long long& c, unsigned long long a,
                                     unsigned long long b) {
    asm("fma.rn.f32x2 %0, %1, %2, %0;" : "+l"(c) : "l"(a), "l"(b));
}
__device__ __forceinline__ void mul2(unsigned long long& c, unsigned long long a) {
    asm("mul.rn.f32x2 %0, %0, %1;" : "+l"(c) : "l"(a));
}
__device__ __forceinline__ float2 up2(unsigned long long v) {
    float lo, hi;
    asm("mov.b64 {%0, %1}, %2;" : "=f"(lo), "=f"(hi) : "l"(v));
    return make_float2(lo, hi);
}

// -------- generic tiled transpose: out[c][r] = in[r][c], batched --------
// element (z, r, c): in[ ib(z) + r*in_rs + c ],  out[ z*out_bs + c*out_rs + r ]
// ib(z) = (z / bsplit)*bs0 + (z % bsplit)*bs1
__global__ void transpose_k(const float* __restrict__ in, float* __restrict__ out,
                            int in_rs, int out_rs, int bsplit,
                            long bs0, long bs1, long out_bs) {
    __shared__ float t[32][33];
    long ib = (long)(blockIdx.z / bsplit) * bs0 + (long)(blockIdx.z % bsplit) * bs1;
    long ob = (long)blockIdx.z * out_bs;
    int r0 = blockIdx.y * 32, c0 = blockIdx.x * 32;
#pragma unroll
    for (int i = threadIdx.y; i < 32; i += 8)
        t[i][threadIdx.x] = in[ib + (long)(r0 + i) * in_rs + c0 + threadIdx.x];
    __syncthreads();
#pragma unroll
    for (int i = threadIdx.y; i < 32; i += 8)
        out[ob + (long)(c0 + i) * out_rs + r0 + threadIdx.x] = t[threadIdx.x][i];
}

// -------- flash attention: one CTA = (n, h, 64-row Q tile) --------
// Qt/Kt: [n,h,d,s] pre-transposed. V: original [n,s,e]. mask: [n,s,s].
__global__ void __launch_bounds__(256) attn_kernel(
    const float* __restrict__ Qt, const float* __restrict__ Kt,
    const float* __restrict__ V,  const int* __restrict__ mask,
    float* __restrict__ X) {
    extern __shared__ float sm[];
    float* Qs = sm;                 // [64][64]  (d-major)
    float* Ks = sm + 64 * 64;       // [64][64]  (d-major)
    float* Vs = sm + 2 * 64 * 64;   // [64][64]  (j-major)
    float* Ps = sm + 3 * 64 * 64;   // [64][68]  (j-major, padded)
    const int PSTR = 68;

    int tid = threadIdx.x;
    int tx = tid & 15, ty = tid >> 4;
    int q0 = blockIdx.x * 64;
    int h  = blockIdx.y;
    int n  = blockIdx.z;
    int nh = n * NHEAD + h;

    const float* Qtb = Qt + (size_t)nh * DHEAD * SEQ;
    const float* Ktb = Kt + (size_t)nh * DHEAD * SEQ;
    const float* Vb  = V + (size_t)n * SEQ * EMB + h * DHEAD;
    const int*   Mb  = mask + (size_t)n * SEQ * SEQ + (size_t)q0 * SEQ;

    // load Q tile once: Qs[d][i] = Qt[d][q0+i]   (coalesced, conflict-free)
    {
        int c4 = tx * 4;
#pragma unroll
        for (int d = ty; d < 64; d += 16)
            *(float4*)(Qs + d * 64 + c4) = *(const float4*)(Qtb + (size_t)d * SEQ + q0 + c4);
    }

    float m[4], l[4];
    unsigned long long o2[4][2];
#pragma unroll
    for (int r = 0; r < 4; r++) { m[r] = -3.0e38f; l[r] = 0.f; o2[r][0] = 0ull; o2[r][1] = 0ull; }

    for (int kt = 0; kt < SEQ / 64; kt++) {
        int k0 = kt * 64;
        __syncthreads();   // protect Ks/Vs/Ps from previous-iteration readers
        {
            int c4 = tx * 4;
#pragma unroll
            for (int d = ty; d < 64; d += 16)
                *(float4*)(Ks + d * 64 + c4) = *(const float4*)(Ktb + (size_t)d * SEQ + k0 + c4);
#pragma unroll
            for (int j = ty; j < 64; j += 16)
                *(float4*)(Vs + j * 64 + c4) = *(const float4*)(Vb + (size_t)(k0 + j) * EMB + c4);
        }
        __syncthreads();

        // S = Q K^T : s2[r][p] = cols (4tx+2p, 4tx+2p+1), rows 4ty+r
        unsigned long long s2[4][2];
#pragma unroll
        for (int r = 0; r < 4; r++) { s2[r][0] = 0ull; s2[r][1] = 0ull; }
#pragma unroll 4
        for (int d = 0; d < 64; d++) {
            float4 a4 = *(const float4*)(Qs + d * 64 + 4 * ty);
            ulonglong2 b = *(const ulonglong2*)(Ks + d * 64 + 4 * tx);
            unsigned long long a0 = pk2(a4.x), a1 = pk2(a4.y), a2 = pk2(a4.z), a3 = pk2(a4.w);
            fma2(s2[0][0], a0, b.x); fma2(s2[0][1], a0, b.y);
            fma2(s2[1][0], a1, b.x); fma2(s2[1][1], a1, b.y);
            fma2(s2[2][0], a2, b.x); fma2(s2[2][1], a2, b.y);
            fma2(s2[3][0], a3, b.x); fma2(s2[3][1], a3, b.y);
        }

        // unpack, mask+scale, online softmax
        float s[4][4], p[4][4];
#pragma unroll
        for (int r = 0; r < 4; r++) {
            float2 u = up2(s2[r][0]), v = up2(s2[r][1]);
            s[r][0] = u.x; s[r][1] = u.y; s[r][2] = v.x; s[r][3] = v.y;
        }
#pragma unroll
        for (int r = 0; r < 4; r++) {
            int4 mv = *(const int4*)(Mb + (size_t)(4 * ty + r) * SEQ + k0 + 4 * tx);
            s[r][0] = mv.x ? s[r][0] * SCALE : MASKED;
            s[r][1] = mv.y ? s[r][1] * SCALE : MASKED;
            s[r][2] = mv.z ? s[r][2] * SCALE : MASKED;
            s[r][3] = mv.w ? s[r][3] * SCALE : MASKED;
        }
#pragma unroll
        for (int r = 0; r < 4; r++) {
            float mx = fmaxf(fmaxf(s[r][0], s[r][1]), fmaxf(s[r][2], s[r][3]));
#pragma unroll
            for (int off = 8; off > 0; off >>= 1)
                mx = fmaxf(mx, __shfl_xor_sync(0xffffffffu, mx, off));
            float mnew  = fmaxf(m[r], mx);
            float alpha = __expf(m[r] - mnew);
            m[r] = mnew;
            p[r][0] = __expf(s[r][0] - mnew);
            p[r][1] = __expf(s[r][1] - mnew);
            p[r][2] = __expf(s[r][2] - mnew);
            p[r][3] = __expf(s[r][3] - mnew);
            float rs = p[r][0] + p[r][1] + p[r][2] + p[r][3];
#pragma unroll
            for (int off = 8; off > 0; off >>= 1)
                rs += __shfl_xor_sync(0xffffffffu, rs, off);
            l[r] = l[r] * alpha + rs;
            unsigned long long al = pk2(alpha);
            mul2(o2[r][0], al);
            mul2(o2[r][1], al);
        }

        // stage P transposed: Ps[j][i]
#pragma unroll
        for (int c = 0; c < 4; c++)
            *(float4*)(Ps + (4 * tx + c) * PSTR + 4 * ty) =
                make_float4(p[0][c], p[1][c], p[2][c], p[3][c]);
        __syncthreads();

        // O += P V : same micro-kernel shape (pairs over d-columns of V)
#pragma unroll 4
        for (int j = 0; j < 64; j++) {
            float4 a4 = *(const float4*)(Ps + j * PSTR + 4 * ty);
            ulonglong2 b = *(const ulonglong2*)(Vs + j * 64 + 4 * tx);
            unsigned long long a0 = pk2(a4.x), a1 = pk2(a4.y), a2 = pk2(a4.z), a3 = pk2(a4.w);
            fma2(o2[0][0], a0, b.x); fma2(o2[0][1], a0, b.y);
            fma2(o2[1][0], a1, b.x); fma2(o2[1][1], a1, b.y);
            fma2(o2[2][0], a2, b.x); fma2(o2[2][1], a2, b.y);
            fma2(o2[3][0], a3, b.x); fma2(o2[3][1], a3, b.y);
        }
    }

    // epilogue: O /= l, write X[n*S+q][h*64+d]
#pragma unroll
    for (int r = 0; r < 4; r++) {
        float inv = 1.0f / l[r];
        float2 u = up2(o2[r][0]), v = up2(o2[r][1]);
        float4 ov = make_float4(u.x * inv, u.y * inv, v.x * inv, v.y * inv);
        *(float4*)(X + (size_t)(n * SEQ + q0 + 4 * ty + r) * EMB + h * DHEAD + 4 * tx) = ov;
    }
}

// -------- fc_out GEMM: Y[m][o] = sum_e Xt[e][m] * Wt[e][o] + b[o] --------
__global__ void __launch_bounds__(256) fc_kernel(
    const float* __restrict__ Xt,   // [E][M]
    const float* __restrict__ Wt,   // [E][O]
    const float* __restrict__ bias, // [O]
    float* __restrict__ Y) {        // [M][O]
    const int M = NB * SEQ;
    __shared__ float Xs[64 * 64];
    __shared__ float Ws[64 * 64];
    int tid = threadIdx.x;
    int tx = tid & 15, ty = tid >> 4;
    int o0 = blockIdx.x * 64, m0 = blockIdx.y * 64;

    unsigned long long acc[4][2];
#pragma unroll
    for (int r = 0; r < 4; r++) { acc[r][0] = 0ull; acc[r][1] = 0ull; }

    for (int e0 = 0; e0 < EMB; e0 += 64) {
        __syncthreads();
        int c4 = tx * 4;
#pragma unroll
        for (int d = ty; d < 64; d += 16) {
            *(float4*)(Xs + d * 64 + c4) = *(const float4*)(Xt + (size_t)(e0 + d) * M + m0 + c4);
            *(float4*)(Ws + d * 64 + c4) = *(const float4*)(Wt + (size_t)(e0 + d) * EMB + o0 + c4);
        }
        __syncthreads();
#pragma unroll 8
        for (int d = 0; d < 64; d++) {
            float4 a4 = *(const float4*)(Xs + d * 64 + 4 * ty);
            ulonglong2 b = *(const ulonglong2*)(Ws + d * 64 + 4 * tx);
            unsigned long long a0 = pk2(a4.x), a1 = pk2(a4.y), a2 = pk2(a4.z), a3 = pk2(a4.w);
            fma2(acc[0][0], a0, b.x); fma2(acc[0][1], a0, b.y);
            fma2(acc[1][0], a1, b.x); fma2(acc[1][1], a1, b.y);
            fma2(acc[2][0], a2, b.x); fma2(acc[2][1], a2, b.y);
            fma2(acc[3][0], a3, b.x); fma2(acc[3][1], a3, b.y);
        }
    }

    float4 bo = *(const float4*)(bias + o0 + 4 * tx);
#pragma unroll
    for (int r = 0; r < 4; r++) {
        float2 u = up2(acc[r][0]), v = up2(acc[r][1]);
        float4 y = make_float4(u.x + bo.x, u.y + bo.y, v.x + bo.z, v.y + bo.w);
        *(float4*)(Y + (size_t)(m0 + 4 * ty + r) * EMB + o0 + 4 * tx) = y;
    }
}

extern "C" void kernel_launch(void* const* d_in, const int* in_sizes, int n_in,
                              void* d_out, int out_size) {
    (void)in_sizes; (void)n_in; (void)out_size;
    const float* values = (const float*)d_in[0];
    const float* keys   = (const float*)d_in[1];
    const float* query  = (const float*)d_in[2];
    const int*   mask   = (const int*)d_in[3];
    const float* Wfc    = (const float*)d_in[4];
    const float* bfc    = (const float*)d_in[5];
    float* out = (float*)d_out;

    float *qt, *kt, *x, *xt, *wt;
    cudaGetSymbolAddress((void**)&qt, g_Qt);
    cudaGetSymbolAddress((void**)&kt, g_Kt);
    cudaGetSymbolAddress((void**)&x,  g_X);
    cudaGetSymbolAddress((void**)&xt, g_Xt);
    cudaGetSymbolAddress((void**)&wt, g_Wt);

    int smem_attn = (3 * 64 * 64 + 64 * 68) * (int)sizeof(float); // 66560 B
    cudaFuncSetAttribute(attn_kernel, cudaFuncAttributeMaxDynamicSharedMemorySize, smem_attn);

    dim3 tb(32, 8);
    // Q,K: [n,s,h*64+d] -> [n,h,d,s]
    transpose_k<<<dim3(DHEAD / 32, SEQ / 32, NB * NHEAD), tb>>>(
        query, qt, EMB, SEQ, NHEAD, (long)SEQ * EMB, DHEAD, (long)DHEAD * SEQ);
    transpose_k<<<dim3(DHEAD / 32, SEQ / 32, NB * NHEAD), tb>>>(
        keys, kt, EMB, SEQ, NHEAD, (long)SEQ * EMB, DHEAD, (long)DHEAD * SEQ);

    attn_kernel<<<dim3(SEQ / 64, NHEAD, NB), 256, smem_attn>>>(qt, kt, values, mask, x);

    // X: [m][e] -> [e][m];  W: [o][e] -> [e][o]
    transpose_k<<<dim3(EMB / 32, (NB * SEQ) / 32, 1), tb>>>(x, xt, EMB, NB * SEQ, 1, 0, 0, 0);
    transpose_k<<<dim3(EMB / 32, EMB / 32, 1), tb>>>(Wfc, wt, EMB, EMB, 1, 0, 0, 0);

    fc_kernel<<<dim3(EMB / 64, (NB * SEQ) / 64), 256>>>(xt, wt, bfc, out);
}